// round 1
// baseline (speedup 1.0000x reference)
#include <cuda_runtime.h>

#define NNF 128
#define MID 32

// Precomputed contraction tables (written by precompute kernels each launch).
__device__ float g_M[9][MID];   // qs monomial vectors in w-space
__device__ float g_G[3][MID];   // qv gamma-path vectors
__device__ float g_H[3][MID];   // qv delta-path vectors
__device__ float g_R[9][NNF];   // qs path projected through Wd_s (scaled)
__device__ float g_S[6][NNF];   // qv path projected through Wd_v (scaled)

// ---------------------------------------------------------------------------
// Precompute stage 1: contract the 32x32x32 tensors with the rank-1 factors.
// grid = 3 blocks (one per tensor family), 1024 threads each: (u, w) = tid.
// ---------------------------------------------------------------------------
__global__ void precompute1_kernel(
    const float* __restrict__ Wa_s, const float* __restrict__ Wa_v,
    const float* __restrict__ b_a,  const float* __restrict__ Wb_s,
    const float* __restrict__ Wb_v, const float* __restrict__ b_b,
    const float* __restrict__ W_ss, const float* __restrict__ W_vv,
    const float* __restrict__ W_sv, const float* __restrict__ W_vs)
{
    __shared__ float sA[MID], sB[MID], sC[MID], sAv[MID], sBv[MID];
    __shared__ float buf[6][MID][MID];

    const int tid = threadIdx.x;
    if (tid < MID) {
        sA[tid]  = Wa_s[tid];
        sB[tid]  = Wb_s[tid];
        sC[tid]  = b_a[tid] + b_b[tid];
        sAv[tid] = Wa_v[tid];
        sBv[tid] = Wb_v[tid];
    }
    __syncthreads();

    const int u = tid >> 5;    // 0..31
    const int w = tid & 31;    // 0..31
    const float Au = sA[u], Bu = sB[u], Cu = sC[u];
    const float Avu = sAv[u], Bvu = sBv[u];

    if (blockIdx.x == 0) {
        // W_ss -> M0..M5 with monomials {a^2, ab, b^2, a, b, 1}
        float m0=0.f,m1=0.f,m2=0.f,m3=0.f,m4=0.f,m5=0.f;
        #pragma unroll 8
        for (int v = 0; v < MID; v++) {
            float t = W_ss[u*1024 + v*32 + w];
            float Av_ = sA[v], Bv_ = sB[v], Cv_ = sC[v];
            m0 += (Au*Av_) * t;
            m1 += (Au*Bv_ + Bu*Av_) * t;
            m2 += (Bu*Bv_) * t;
            m3 += (Au*Cv_ + Cu*Av_) * t;
            m4 += (Bu*Cv_ + Cu*Bv_) * t;
            m5 += (Cu*Cv_) * t;
        }
        buf[0][u][w]=m0; buf[1][u][w]=m1; buf[2][u][w]=m2;
        buf[3][u][w]=m3; buf[4][u][w]=m4; buf[5][u][w]=m5;
        __syncthreads();
        if (tid < 6*MID) {
            int k = tid >> 5, ww = tid & 31;
            float s = 0.f;
            #pragma unroll
            for (int uu = 0; uu < MID; uu++) s += buf[k][uu][ww];
            g_M[k][ww] = s;
        }
    } else if (blockIdx.x == 1) {
        // W_vv -> M6..M8 with monomials {|g|^2, g.d, |d|^2}
        float m0=0.f,m1=0.f,m2=0.f;
        #pragma unroll 8
        for (int v = 0; v < MID; v++) {
            float t = W_vv[u*1024 + v*32 + w];
            float Avv = sAv[v], Bvv = sBv[v];
            m0 += (Avu*Avv) * t;
            m1 += (Avu*Bvv + Bvu*Avv) * t;
            m2 += (Bvu*Bvv) * t;
        }
        buf[0][u][w]=m0; buf[1][u][w]=m1; buf[2][u][w]=m2;
        __syncthreads();
        if (tid < 3*MID) {
            int k = tid >> 5, ww = tid & 31;
            float s = 0.f;
            #pragma unroll
            for (int uu = 0; uu < MID; uu++) s += buf[k][uu][ww];
            g_M[6+k][ww] = s;
        }
    } else {
        // W_sv + W_vs -> G1..3 (gamma path), H1..3 (delta path)
        float g1=0.f,g2=0.f,g3=0.f,h1=0.f,h2=0.f,h3=0.f;
        #pragma unroll 8
        for (int v = 0; v < MID; v++) {
            float t = W_sv[u*1024 + v*32 + w];
            float Avv = sAv[v], Bvv = sBv[v];
            g1 += (Au*Avv) * t;  g2 += (Bu*Avv) * t;  g3 += (Cu*Avv) * t;
            h1 += (Au*Bvv) * t;  h2 += (Bu*Bvv) * t;  h3 += (Cu*Bvv) * t;
        }
        #pragma unroll 8
        for (int v = 0; v < MID; v++) {
            float t = W_vs[u*1024 + v*32 + w];
            float Av_ = sA[v], Bv_ = sB[v], Cv_ = sC[v];
            g1 += (Avu*Av_) * t;  g2 += (Avu*Bv_) * t;  g3 += (Avu*Cv_) * t;
            h1 += (Bvu*Av_) * t;  h2 += (Bvu*Bv_) * t;  h3 += (Bvu*Cv_) * t;
        }
        buf[0][u][w]=g1; buf[1][u][w]=g2; buf[2][u][w]=g3;
        buf[3][u][w]=h1; buf[4][u][w]=h2; buf[5][u][w]=h3;
        __syncthreads();
        if (tid < 6*MID) {
            int k = tid >> 5, ww = tid & 31;
            float s = 0.f;
            #pragma unroll
            for (int uu = 0; uu < MID; uu++) s += buf[k][uu][ww];
            if (k < 3) g_G[k][ww] = s; else g_H[k-3][ww] = s;
        }
    }
}

// ---------------------------------------------------------------------------
// Precompute stage 2: project through Wd_s / Wd_v, fold all scalar prefactors.
// 1 block x 128 threads (one per feature index v').
// ---------------------------------------------------------------------------
__global__ void precompute2_kernel(const float* __restrict__ Wd_s,
                                   const float* __restrict__ Wd_v)
{
    const int vp = threadIdx.x; // 0..127
    const double INV_SQRT3 = 0.5773502691896258;
    const double PW_QQ_S = 0.02209708691207961;   // sqrt(1/2048)
    const double PW_QQ_V = 0.03827327723098713;   // sqrt(3/2048)
    const double PW_DOWN = 0.011048543456039805;  // sqrt(1/8192)
    const float scR  = (float)(PW_DOWN * PW_QQ_S);                        // qs, ss-part
    const float scR3 = (float)(PW_DOWN * PW_QQ_S * INV_SQRT3);            // qs, vv-part
    const float scS  = (float)(PW_DOWN * INV_SQRT3 * PW_QQ_V * INV_SQRT3);// qv path

    #pragma unroll
    for (int k = 0; k < 9; k++) {
        float s = 0.f;
        #pragma unroll
        for (int uu = 0; uu < MID; uu++) s += g_M[k][uu] * Wd_s[uu*NNF + vp];
        g_R[k][vp] = s * (k < 6 ? scR : scR3);
    }
    #pragma unroll
    for (int k = 0; k < 3; k++) {
        float sg = 0.f, sh = 0.f;
        #pragma unroll
        for (int uu = 0; uu < MID; uu++) {
            float wd = Wd_v[uu*NNF + vp];
            sg += g_G[k][uu] * wd;
            sh += g_H[k][uu] * wd;
        }
        g_S[k][vp]   = sg * scS;
        g_S[3+k][vp] = sh * scS;
    }
}

// ---------------------------------------------------------------------------
// Main kernel: one warp per node, grid-stride. Streams node_feats once.
// Tables live in registers (15 x float4 per lane). Warp-shuffle reduce.
// ---------------------------------------------------------------------------
__global__ void __launch_bounds__(256) energy_kernel(
    const float* __restrict__ nf,
    const float* __restrict__ c0,
    const float* __restrict__ ci,
    float* __restrict__ out, int N)
{
    const int lane   = threadIdx.x & 31;
    const int warp   = (blockIdx.x * blockDim.x + threadIdx.x) >> 5;
    const int nwarps = (gridDim.x * blockDim.x) >> 5;

    float R[9][4], S[6][4];
    #pragma unroll
    for (int k = 0; k < 9; k++) {
        float4 t = *(const float4*)&g_R[k][lane*4];
        R[k][0]=t.x; R[k][1]=t.y; R[k][2]=t.z; R[k][3]=t.w;
    }
    #pragma unroll
    for (int k = 0; k < 6; k++) {
        float4 t = *(const float4*)&g_S[k][lane*4];
        S[k][0]=t.x; S[k][1]=t.y; S[k][2]=t.z; S[k][3]=t.w;
    }

    for (int n = warp; n < N; n += nwarps) {
        const float* row = nf + (size_t)n * (4*NNF);
        // issue all independent loads up front (MLP)
        float4 fs  = *(const float4*)(row + lane*4);
        const float* rv = row + NNF + 12*lane;      // 16B-aligned: 12*lane % 4 == 0
        float4 fv0 = *(const float4*)(rv);
        float4 fv1 = *(const float4*)(rv + 4);
        float4 fv2 = *(const float4*)(rv + 8);
        float4 q0  = *(const float4*)(c0 + 4*(size_t)n);
        float4 qi  = *(const float4*)(ci + 4*(size_t)n);

        const float a = qi.x, b = q0.x;
        const float g0 = qi.y, g1 = qi.z, g2 = qi.w;
        const float d0 = q0.y, d1 = q0.z, d2 = q0.w;
        const float ca2 = a*a, cab = a*b, cb2 = b*b;
        const float cg2 = g0*g0 + g1*g1 + g2*g2;
        const float cgd = g0*d0 + g1*d1 + g2*d2;
        const float cd2 = d0*d0 + d1*d1 + d2*d2;

        const float fsv[4] = {fs.x, fs.y, fs.z, fs.w};
        const float fv[12] = {fv0.x,fv0.y,fv0.z,fv0.w,
                              fv1.x,fv1.y,fv1.z,fv1.w,
                              fv2.x,fv2.y,fv2.z,fv2.w};

        float acc = 0.f;
        #pragma unroll
        for (int j = 0; j < 4; j++) {
            // qs path: T[v] = sum_k coef_k * R_k[v]
            float t = R[5][j];
            t += ca2*R[0][j] + cab*R[1][j] + cb2*R[2][j];
            t += a  *R[3][j] + b  *R[4][j];
            t += cg2*R[6][j] + cgd*R[7][j] + cd2*R[8][j];
            acc += fsv[j] * t;
            // qv path
            const float x0 = fv[3*j], x1 = fv[3*j+1], x2 = fv[3*j+2];
            const float xg = g0*x0 + g1*x1 + g2*x2;
            const float xd = d0*x0 + d1*x1 + d2*x2;
            const float sg = S[2][j] + a*S[0][j] + b*S[1][j];
            const float sh = S[5][j] + a*S[3][j] + b*S[4][j];
            acc += xg*sg + xd*sh;
        }

        #pragma unroll
        for (int off = 16; off; off >>= 1)
            acc += __shfl_down_sync(0xffffffffu, acc, off);
        if (lane == 0) out[n] = acc;
    }
}

// ---------------------------------------------------------------------------
// Input order (metadata): 0 node_feats, 1 charges_0, 2 charges_induced,
// 3 edge_feats, 4 edge_attrs, 5 field_feats, 6 edge_index, 7 batch,
// 8 Wa_s, 9 Wa_v, 10 b_a, 11 Wb_s, 12 Wb_v, 13 b_b,
// 14 W_ss, 15 W_vv, 16 W_sv, 17 W_vs, 18 Wd_s, 19 Wd_v.  Output: energy (N,)
// ---------------------------------------------------------------------------
extern "C" void kernel_launch(void* const* d_in, const int* in_sizes, int n_in,
                              void* d_out, int out_size)
{
    const float* node_feats = (const float*)d_in[0];
    const float* charges_0  = (const float*)d_in[1];
    const float* charges_i  = (const float*)d_in[2];
    const float* Wa_s = (const float*)d_in[8];
    const float* Wa_v = (const float*)d_in[9];
    const float* b_a  = (const float*)d_in[10];
    const float* Wb_s = (const float*)d_in[11];
    const float* Wb_v = (const float*)d_in[12];
    const float* b_b  = (const float*)d_in[13];
    const float* W_ss = (const float*)d_in[14];
    const float* W_vv = (const float*)d_in[15];
    const float* W_sv = (const float*)d_in[16];
    const float* W_vs = (const float*)d_in[17];
    const float* Wd_s = (const float*)d_in[18];
    const float* Wd_v = (const float*)d_in[19];
    float* out = (float*)d_out;
    const int N = out_size;

    precompute1_kernel<<<3, 1024>>>(Wa_s, Wa_v, b_a, Wb_s, Wb_v, b_b,
                                    W_ss, W_vv, W_sv, W_vs);
    precompute2_kernel<<<1, NNF>>>(Wd_s, Wd_v);
    energy_kernel<<<1184, 256>>>(node_feats, charges_0, charges_i, out, N);
}

// round 2
// speedup vs baseline: 1.4338x; 1.4338x over previous
#include <cuda_runtime.h>

#define NNF 128
#define MID 32
typedef unsigned long long u64;

// Staging + final tables
__device__ float g_stage[3][32][6][32];
__device__ float g_R[9][NNF];   // qs path projected through Wd_s (scaled)
__device__ float g_S[6][NNF];   // qv path projected through Wd_v (scaled)

// ---- packed f32x2 helpers -------------------------------------------------
__device__ __forceinline__ u64 pk2(float lo, float hi) {
    u64 r; asm("mov.b64 %0,{%1,%2};" : "=l"(r) : "f"(lo), "f"(hi)); return r;
}
__device__ __forceinline__ void upk2(u64 a, float& lo, float& hi) {
    asm("mov.b64 {%0,%1},%2;" : "=f"(lo), "=f"(hi) : "l"(a));
}
__device__ __forceinline__ u64 fma2(u64 a, u64 b, u64 c) {
    u64 d; asm("fma.rn.f32x2 %0,%1,%2,%3;" : "=l"(d) : "l"(a), "l"(b), "l"(c)); return d;
}
__device__ __forceinline__ u64 mul2(u64 a, u64 b) {
    u64 d; asm("mul.rn.f32x2 %0,%1,%2;" : "=l"(d) : "l"(a), "l"(b)); return d;
}
__device__ __forceinline__ u64 add2(u64 a, u64 b) {
    u64 d; asm("add.rn.f32x2 %0,%1,%2;" : "=l"(d) : "l"(a), "l"(b)); return d;
}

// ---------------------------------------------------------------------------
// Precompute stage 1: 96 blocks = 3 families x 32 u-slices. One element/thread.
// ---------------------------------------------------------------------------
__global__ void precompute1_kernel(
    const float* __restrict__ Wa_s, const float* __restrict__ Wa_v,
    const float* __restrict__ b_a,  const float* __restrict__ Wb_s,
    const float* __restrict__ Wb_v, const float* __restrict__ b_b,
    const float* __restrict__ W_ss, const float* __restrict__ W_vv,
    const float* __restrict__ W_sv, const float* __restrict__ W_vs)
{
    __shared__ float sA[MID], sB[MID], sC[MID], sAv[MID], sBv[MID];
    __shared__ float buf[6][32][33];

    const int tid = threadIdx.x;
    const int fam = blockIdx.x >> 5;
    const int u   = blockIdx.x & 31;
    if (tid < MID) {
        sA[tid]  = Wa_s[tid];
        sB[tid]  = Wb_s[tid];
        sC[tid]  = b_a[tid] + b_b[tid];
        sAv[tid] = Wa_v[tid];
        sBv[tid] = Wb_v[tid];
    }
    __syncthreads();

    const int v = tid >> 5;
    const int w = tid & 31;
    const int idx = u * 1024 + v * 32 + w;
    int nk;

    if (fam == 0) {
        float t = W_ss[idx];
        float Au = sA[u], Bu = sB[u], Cu = sC[u];
        float Av = sA[v], Bv = sB[v], Cv = sC[v];
        buf[0][v][w] = (Au * Av) * t;
        buf[1][v][w] = (Au * Bv + Bu * Av) * t;
        buf[2][v][w] = (Bu * Bv) * t;
        buf[3][v][w] = (Au * Cv + Cu * Av) * t;
        buf[4][v][w] = (Bu * Cv + Cu * Bv) * t;
        buf[5][v][w] = (Cu * Cv) * t;
        nk = 6;
    } else if (fam == 1) {
        float t = W_vv[idx];
        float Avu = sAv[u], Bvu = sBv[u], Avv = sAv[v], Bvv = sBv[v];
        buf[0][v][w] = (Avu * Avv) * t;
        buf[1][v][w] = (Avu * Bvv + Bvu * Avv) * t;
        buf[2][v][w] = (Bvu * Bvv) * t;
        nk = 3;
    } else {
        float tsv = W_sv[idx];
        float tvs = W_vs[idx];
        float Au = sA[u], Bu = sB[u], Cu = sC[u];
        float Avu = sAv[u], Bvu = sBv[u];
        float Av = sA[v], Bv = sB[v], Cv = sC[v];
        float Avv = sAv[v], Bvv = sBv[v];
        buf[0][v][w] = Au * Avv * tsv + Avu * Av * tvs;
        buf[1][v][w] = Bu * Avv * tsv + Avu * Bv * tvs;
        buf[2][v][w] = Cu * Avv * tsv + Avu * Cv * tvs;
        buf[3][v][w] = Au * Bvv * tsv + Bvu * Av * tvs;
        buf[4][v][w] = Bu * Bvv * tsv + Bvu * Bv * tvs;
        buf[5][v][w] = Cu * Bvv * tsv + Bvu * Cv * tvs;
        nk = 6;
    }
    __syncthreads();

    if (tid < nk * 32) {
        const int k = tid >> 5, ww = tid & 31;
        float s = 0.f;
        #pragma unroll
        for (int vv = 0; vv < 32; vv++) s += buf[k][vv][ww];
        g_stage[fam][u][k][ww] = s;
    }
}

// ---------------------------------------------------------------------------
// Precompute stage 2: u-reduction of stage buffer, then Wd projection + scales.
// 1 block x 512 threads.
// ---------------------------------------------------------------------------
__global__ void precompute2_kernel(const float* __restrict__ Wd_s,
                                   const float* __restrict__ Wd_v)
{
    __shared__ float sM[9][32], sG[3][32], sH[3][32];
    const int tid = threadIdx.x;

    if (tid < 480) {
        const int w = tid & 31;
        float s = 0.f;
        if (tid < 192) {
            const int k = tid >> 5;
            #pragma unroll
            for (int u = 0; u < 32; u++) s += g_stage[0][u][k][w];
            sM[k][w] = s;
        } else if (tid < 288) {
            const int k = (tid - 192) >> 5;
            #pragma unroll
            for (int u = 0; u < 32; u++) s += g_stage[1][u][k][w];
            sM[6 + k][w] = s;
        } else {
            const int k = (tid - 288) >> 5;
            #pragma unroll
            for (int u = 0; u < 32; u++) s += g_stage[2][u][k][w];
            if (k < 3) sG[k][w] = s; else sH[k - 3][w] = s;
        }
    }
    __syncthreads();

    if (tid < NNF) {
        const int vp = tid;
        const double INV_SQRT3 = 0.5773502691896258;
        const double PW_QQ_S = 0.02209708691207961;   // sqrt(1/2048)
        const double PW_QQ_V = 0.03827327723098713;   // sqrt(3/2048)
        const double PW_DOWN = 0.011048543456039805;  // sqrt(1/8192)
        const float scR  = (float)(PW_DOWN * PW_QQ_S);
        const float scR3 = (float)(PW_DOWN * PW_QQ_S * INV_SQRT3);
        const float scS  = (float)(PW_DOWN * INV_SQRT3 * PW_QQ_V * INV_SQRT3);

        #pragma unroll
        for (int k = 0; k < 9; k++) {
            float s = 0.f;
            #pragma unroll
            for (int uu = 0; uu < MID; uu++) s += sM[k][uu] * Wd_s[uu * NNF + vp];
            g_R[k][vp] = s * (k < 6 ? scR : scR3);
        }
        #pragma unroll
        for (int k = 0; k < 3; k++) {
            float sg = 0.f, sh = 0.f;
            #pragma unroll
            for (int uu = 0; uu < MID; uu++) {
                float wd = Wd_v[uu * NNF + vp];
                sg += sG[k][uu] * wd;
                sh += sH[k][uu] * wd;
            }
            g_S[k][vp]     = sg * scS;
            g_S[3 + k][vp] = sh * scS;
        }
    }
}

// ---------------------------------------------------------------------------
// Per-node partial (per-lane, 4 features) using packed f32x2 math.
// ---------------------------------------------------------------------------
__device__ __forceinline__ float node_partial(
    const u64 R2[9][2], const u64 S2[6][2],
    float4 fs, const float* fv, float4 q0, float4 qi)
{
    const float a = qi.x, b = q0.x;
    const float g0 = qi.y, g1 = qi.z, g2 = qi.w;
    const float d0 = q0.y, d1 = q0.z, d2 = q0.w;
    const float ca2 = a * a, cab = a * b, cb2 = b * b;
    const float cg2 = g0 * g0 + g1 * g1 + g2 * g2;
    const float cgd = g0 * d0 + g1 * d1 + g2 * d2;
    const float cd2 = d0 * d0 + d1 * d1 + d2 * d2;

    const u64 C0 = pk2(ca2, ca2), C1 = pk2(cab, cab), C2 = pk2(cb2, cb2);
    const u64 CA = pk2(a, a),     CB = pk2(b, b);
    const u64 C6 = pk2(cg2, cg2), C7 = pk2(cgd, cgd), C8 = pk2(cd2, cd2);
    const u64 G0 = pk2(g0, g0), G1 = pk2(g1, g1), G2 = pk2(g2, g2);
    const u64 D0 = pk2(d0, d0), D1 = pk2(d1, d1), D2 = pk2(d2, d2);

    const u64 fs2[2] = { pk2(fs.x, fs.y), pk2(fs.z, fs.w) };

    u64 acc = pk2(0.f, 0.f);
    #pragma unroll
    for (int h = 0; h < 2; h++) {
        // qs path
        u64 t = fma2(C0, R2[0][h], R2[5][h]);
        t = fma2(C1, R2[1][h], t);
        t = fma2(C2, R2[2][h], t);
        t = fma2(CA, R2[3][h], t);
        t = fma2(CB, R2[4][h], t);
        t = fma2(C6, R2[6][h], t);
        t = fma2(C7, R2[7][h], t);
        t = fma2(C8, R2[8][h], t);
        acc = fma2(fs2[h], t, acc);
        // qv path: feature pair (2h, 2h+1)
        const u64 x0 = pk2(fv[6 * h + 0], fv[6 * h + 3]);
        const u64 x1 = pk2(fv[6 * h + 1], fv[6 * h + 4]);
        const u64 x2 = pk2(fv[6 * h + 2], fv[6 * h + 5]);
        u64 xg = mul2(G0, x0);
        xg = fma2(G1, x1, xg);
        xg = fma2(G2, x2, xg);
        u64 xd = mul2(D0, x0);
        xd = fma2(D1, x1, xd);
        xd = fma2(D2, x2, xd);
        u64 sg = fma2(CA, S2[0][h], S2[2][h]);
        sg = fma2(CB, S2[1][h], sg);
        u64 sh = fma2(CA, S2[3][h], S2[5][h]);
        sh = fma2(CB, S2[4][h], sh);
        acc = fma2(xg, sg, acc);
        acc = fma2(xd, sh, acc);
    }
    float lo, hi;
    upk2(acc, lo, hi);
    return lo + hi;
}

// ---------------------------------------------------------------------------
// Main kernel: one warp per node-PAIR, grid-stride. Streams node_feats once.
// ---------------------------------------------------------------------------
__global__ void __launch_bounds__(256) energy_kernel(
    const float* __restrict__ nf,
    const float* __restrict__ c0,
    const float* __restrict__ ci,
    float* __restrict__ out, int N)
{
    const int lane   = threadIdx.x & 31;
    const int warp   = (blockIdx.x * blockDim.x + threadIdx.x) >> 5;
    const int nwarps = (gridDim.x * blockDim.x) >> 5;

    // Pack tables along the feature axis: pairs (4l+0,4l+1) and (4l+2,4l+3).
    u64 R2[9][2], S2[6][2];
    #pragma unroll
    for (int k = 0; k < 9; k++) {
        float4 t = *(const float4*)&g_R[k][lane * 4];
        R2[k][0] = pk2(t.x, t.y); R2[k][1] = pk2(t.z, t.w);
    }
    #pragma unroll
    for (int k = 0; k < 6; k++) {
        float4 t = *(const float4*)&g_S[k][lane * 4];
        S2[k][0] = pk2(t.x, t.y); S2[k][1] = pk2(t.z, t.w);
    }

    const int pairs = N >> 1;
    for (int p = warp; p < pairs; p += nwarps) {
        const int n0 = 2 * p;
        const float* rowA = nf + (size_t)n0 * (4 * NNF);
        const float* rowB = rowA + 4 * NNF;

        // Batch all 12 loads up front (MLP).
        float4 fsA  = *(const float4*)(rowA + lane * 4);
        float4 fsB  = *(const float4*)(rowB + lane * 4);
        const float* rvA = rowA + NNF + 12 * lane;
        const float* rvB = rowB + NNF + 12 * lane;
        float4 fvA0 = *(const float4*)(rvA);
        float4 fvA1 = *(const float4*)(rvA + 4);
        float4 fvA2 = *(const float4*)(rvA + 8);
        float4 fvB0 = *(const float4*)(rvB);
        float4 fvB1 = *(const float4*)(rvB + 4);
        float4 fvB2 = *(const float4*)(rvB + 8);
        float4 q0A  = *(const float4*)(c0 + 4 * (size_t)n0);
        float4 qiA  = *(const float4*)(ci + 4 * (size_t)n0);
        float4 q0B  = *(const float4*)(c0 + 4 * (size_t)n0 + 4);
        float4 qiB  = *(const float4*)(ci + 4 * (size_t)n0 + 4);

        const float fvA[12] = {fvA0.x, fvA0.y, fvA0.z, fvA0.w,
                               fvA1.x, fvA1.y, fvA1.z, fvA1.w,
                               fvA2.x, fvA2.y, fvA2.z, fvA2.w};
        const float fvB[12] = {fvB0.x, fvB0.y, fvB0.z, fvB0.w,
                               fvB1.x, fvB1.y, fvB1.z, fvB1.w,
                               fvB2.x, fvB2.y, fvB2.z, fvB2.w};

        const float accA = node_partial(R2, S2, fsA, fvA, q0A, qiA);
        const float accB = node_partial(R2, S2, fsB, fvB, q0B, qiB);

        // Joint packed warp reduction for both nodes.
        u64 pr = pk2(accA, accB);
        #pragma unroll
        for (int off = 16; off; off >>= 1)
            pr = add2(pr, __shfl_down_sync(0xffffffffu, pr, off));
        if (lane == 0) {
            float2 o;
            upk2(pr, o.x, o.y);
            *(float2*)(out + n0) = o;
        }
    }

    // Odd-N tail (not hit for N=131072, kept for generality).
    if ((N & 1) && warp == 0) {
        const int n = N - 1;
        const float* row = nf + (size_t)n * (4 * NNF);
        float4 fs  = *(const float4*)(row + lane * 4);
        const float* rv = row + NNF + 12 * lane;
        float4 f0 = *(const float4*)(rv);
        float4 f1 = *(const float4*)(rv + 4);
        float4 f2 = *(const float4*)(rv + 8);
        float4 q0 = *(const float4*)(c0 + 4 * (size_t)n);
        float4 qi = *(const float4*)(ci + 4 * (size_t)n);
        const float fv[12] = {f0.x, f0.y, f0.z, f0.w, f1.x, f1.y, f1.z, f1.w,
                              f2.x, f2.y, f2.z, f2.w};
        float acc = node_partial(R2, S2, fs, fv, q0, qi);
        #pragma unroll
        for (int off = 16; off; off >>= 1)
            acc += __shfl_down_sync(0xffffffffu, acc, off);
        if (lane == 0) out[n] = acc;
    }
}

// ---------------------------------------------------------------------------
extern "C" void kernel_launch(void* const* d_in, const int* in_sizes, int n_in,
                              void* d_out, int out_size)
{
    const float* node_feats = (const float*)d_in[0];
    const float* charges_0  = (const float*)d_in[1];
    const float* charges_i  = (const float*)d_in[2];
    const float* Wa_s = (const float*)d_in[8];
    const float* Wa_v = (const float*)d_in[9];
    const float* b_a  = (const float*)d_in[10];
    const float* Wb_s = (const float*)d_in[11];
    const float* Wb_v = (const float*)d_in[12];
    const float* b_b  = (const float*)d_in[13];
    const float* W_ss = (const float*)d_in[14];
    const float* W_vv = (const float*)d_in[15];
    const float* W_sv = (const float*)d_in[16];
    const float* W_vs = (const float*)d_in[17];
    const float* Wd_s = (const float*)d_in[18];
    const float* Wd_v = (const float*)d_in[19];
    float* out = (float*)d_out;
    const int N = out_size;

    precompute1_kernel<<<96, 1024>>>(Wa_s, Wa_v, b_a, Wb_s, Wb_v, b_b,
                                     W_ss, W_vv, W_sv, W_vs);
    precompute2_kernel<<<1, 512>>>(Wd_s, Wd_v);
    energy_kernel<<<1184, 256>>>(node_feats, charges_0, charges_i, out, N);
}